// round 6
// baseline (speedup 1.0000x reference)
#include <cuda_runtime.h>

// ---------------------------------------------------------------------------
// DECOLA Stage2 assigner — label-bucketed, smem-staged column pass.
// Inputs (metadata order):
//   0: pred_logits_match (B,N,1) f32   -- unused
//   1: pred_boxes        (B,N,4) f32   -- unused
//   2: init_reference    (B,N,4) f32   -- proposals (cxcywh)
//   3: prompt_inds       (B,N)   i32
//   4: gt_labels         (B,M)   i32
//   5: gt_boxes          (B,M,4) f32
//   6: max_k             scalar  i32   (k derived from out_size)
// Output: concat(rows, cols, valid, sel_iou) each (B,M,k), float32.
// ---------------------------------------------------------------------------

#define BB      16            // batch (fixed for this problem)
#define NL      128           // label slots (L=80, padded)
#define PCAP    256           // proposal bucket capacity (mean 37.5)
#define GCAP    64            // gt bucket capacity (mean 3.75)
#define NBK     (BB * NL)     // 2048 buckets
#define MAX_BN  49152
#define MAX_BM  8192
#define MAXM    512           // smem staging capacity per batch (M=300)
#define TOPK    4
#define IMAXI   0x7fffffff

// NOTE: __device__ globals have static storage -> zero-initialized at module
// load. Counters are re-zeroed at the END of each call (in k_out), so every
// invocation starts clean without a dedicated zeroing launch.
__device__ float4 g_pxy[MAX_BN];
__device__ float  g_pa [MAX_BN];
__device__ float4 g_gxy[MAX_BM];
__device__ float  g_ga [MAX_BM];
__device__ int    d_pcnt[NBK];
__device__ float4 p_bx[NBK * PCAP];
__device__ float  p_ba[NBK * PCAP];
__device__ int    p_bi[NBK * PCAP];
__device__ int    d_gcnt[NBK];
__device__ float4 gt_bx[NBK * GCAP];
__device__ float  gt_ba[NBK * GCAP];
__device__ int    gt_bm[NBK * GCAP];
__device__ float  g_gmax[MAX_BM];
__device__ float  g_topv[MAX_BM * TOPK];
__device__ int    g_topi[MAX_BM * TOPK];
__device__ int    g_cnt [MAX_BM];

// IoU from explicit _rn intrinsics so row pass and column pass are
// BITWISE identical (lq needs v == gmax).
__device__ __forceinline__ float iou_fn(float4 g, float ga, float4 p, float pa) {
    float x0 = fmaxf(g.x, p.x);
    float y0 = fmaxf(g.y, p.y);
    float x1 = fminf(g.z, p.z);
    float y1 = fminf(g.w, p.w);
    float w  = fmaxf(__fsub_rn(x1, x0), 0.0f);
    float h  = fmaxf(__fsub_rn(y1, y0), 0.0f);
    float it = __fmul_rn(w, h);
    float un = __fsub_rn(__fadd_rn(ga, pa), it);
    return __fdiv_rn(it, fmaxf(un, 1e-9f));
}

// Insert (v,i) into 4-entry list sorted by (value desc, index asc).
// Strict total order (indices distinct) -> insert-order independent,
// matches jax.lax.top_k stability.
__device__ __forceinline__ void ins4(float v, int i, float tv[TOPK], int ti[TOPK]) {
    if (v > tv[3] || (v == tv[3] && i < ti[3])) {
        if (v > tv[2] || (v == tv[2] && i < ti[2])) {
            tv[3] = tv[2]; ti[3] = ti[2];
            if (v > tv[1] || (v == tv[1] && i < ti[1])) {
                tv[2] = tv[1]; ti[2] = ti[1];
                if (v > tv[0] || (v == tv[0] && i < ti[0])) {
                    tv[1] = tv[0]; ti[1] = ti[0];
                    tv[0] = v;     ti[0] = i;
                } else { tv[1] = v; ti[1] = i; }
            } else { tv[2] = v; ti[2] = i; }
        } else { tv[3] = v; ti[3] = i; }
    }
}

__device__ __forceinline__ float4 cxcywh_to_xyxy(float4 c) {
    float4 x;
    x.x = c.x - 0.5f * c.z; x.y = c.y - 0.5f * c.w;
    x.z = c.x + 0.5f * c.z; x.w = c.y + 0.5f * c.w;
    return x;
}

// ---------------- Kernel 1: convert + bucket-scatter ----------------
__global__ void k_build(const float4* __restrict__ props,
                        const float4* __restrict__ gts,
                        const int* __restrict__ pinds,
                        const int* __restrict__ glabels,
                        int BN, int BM, int N, int M) {
    int idx = blockIdx.x * blockDim.x + threadIdx.x;
    if (idx < BN) {
        float4 x = cxcywh_to_xyxy(props[idx]);
        float  a = __fmul_rn(__fsub_rn(x.z, x.x), __fsub_rn(x.w, x.y));
        g_pxy[idx] = x;
        g_pa [idx] = a;
        int b  = idx / N;
        int bk = b * NL + pinds[idx];
        int s  = atomicAdd(&d_pcnt[bk], 1);
        if (s < PCAP) {
            p_bx[bk * PCAP + s] = x;
            p_ba[bk * PCAP + s] = a;
            p_bi[bk * PCAP + s] = idx - b * N;
        }
    } else if (idx < BN + BM) {
        int j = idx - BN;
        float4 x = cxcywh_to_xyxy(gts[j]);
        float  a = __fmul_rn(__fsub_rn(x.z, x.x), __fsub_rn(x.w, x.y));
        g_gxy[j] = x;
        g_ga [j] = a;
        int b  = j / M;
        int bk = b * NL + glabels[j];
        int s  = atomicAdd(&d_gcnt[bk], 1);
        if (s < GCAP) {
            gt_bx[bk * GCAP + s] = x;
            gt_ba[bk * GCAP + s] = a;
            gt_bm[bk * GCAP + s] = j - b * M;
        }
    }
}

// -------- Kernel 2: 8 lanes per GT row: gmax + stable top-4 --------
__global__ __launch_bounds__(256) void k_rows(
        const int* __restrict__ glabels, int M, int BM) {
    int t    = blockIdx.x * blockDim.x + threadIdx.x;
    int bm   = t >> 3;                  // 8 lanes per GT
    if (bm >= BM) return;               // uniform per 8-lane group
    int sub  = t & 7;
    int b    = bm / M;
    int bk   = b * NL + glabels[bm];
    int cnt  = min(d_pcnt[bk], PCAP);
    int base = bk * PCAP;

    float4 g = g_gxy[bm];
    float ga = g_ga[bm];

    float tv[TOPK] = {-1.f, -1.f, -1.f, -1.f};
    int   ti[TOPK] = {IMAXI, IMAXI, IMAXI, IMAXI};

    for (int e = sub; e < cnt; e += 8) {
        float v = iou_fn(g, ga, p_bx[base + e], p_ba[base + e]);
        ins4(v, p_bi[base + e], tv, ti);
    }

    // 3-step butterfly within each 8-lane group (xor of low 3 lane bits).
#pragma unroll
    for (int off = 4; off > 0; off >>= 1) {
        float ov[TOPK]; int oi[TOPK];
#pragma unroll
        for (int j = 0; j < TOPK; j++) {
            ov[j] = __shfl_xor_sync(0xffffffffu, tv[j], off);
            oi[j] = __shfl_xor_sync(0xffffffffu, ti[j], off);
        }
#pragma unroll
        for (int j = 0; j < TOPK; j++) ins4(ov[j], oi[j], tv, ti);
    }

    if (sub == 0) {
        g_gmax[bm] = tv[0];              // -1 when no matched proposal (== ref NEG)
#pragma unroll
        for (int j = 0; j < TOPK; j++) {
            g_topv[bm * TOPK + j] = tv[j];
            g_topi[bm * TOPK + j] = ti[j];
        }
    }
}

// -------- Kernel 3: column pass with smem-staged GT set --------
// One block per (n-tile, batch). All of batch b's GT bucket data (~M entries)
// is compacted into shared memory once per block; the per-proposal scan then
// runs entirely out of LDS.
__global__ __launch_bounds__(256) void k_cols(
        const int* __restrict__ pinds, int N, int M) {
    __shared__ int    soff[NL + 1];
    __shared__ float4 s_box [MAXM];
    __shared__ float  s_area[MAXM];
    __shared__ float  s_gm  [MAXM];
    __shared__ int    s_m   [MAXM];

    int b   = blockIdx.y;
    int tid = threadIdx.x;

    // --- per-label counts + Hillis-Steele prefix sum over NL=128 labels ---
    int mycnt = 0;
    if (tid < NL) {
        mycnt = min(d_gcnt[b * NL + tid], GCAP);
        soff[tid + 1] = mycnt;
        if (tid == 0) soff[0] = 0;
    }
    __syncthreads();
#pragma unroll
    for (int d = 1; d < NL; d <<= 1) {
        int v = 0;
        if (tid < NL) {
            v = soff[tid + 1];
            if (tid + 1 > d) v += soff[tid + 1 - d];
        }
        __syncthreads();
        if (tid < NL) soff[tid + 1] = v;
        __syncthreads();
    }

    // --- stage bucket entries compactly ---
    if (tid < NL) {
        int base = (b * NL + tid) * GCAP;
        int o    = soff[tid];
        for (int s = 0; s < mycnt; s++) {
            s_box [o + s] = gt_bx[base + s];
            s_area[o + s] = gt_ba[base + s];
            int m         = gt_bm[base + s];
            s_m   [o + s] = m;
            s_gm  [o + s] = g_gmax[b * M + m];
        }
    }
    __syncthreads();

    int n = blockIdx.x * blockDim.x + tid;
    if (n >= N) return;

    int    pv = pinds[b * N + n];
    float4 p  = g_pxy[b * N + n];
    float  pa = g_pa [b * N + n];

    int o0 = soff[pv];
    int o1 = soff[pv + 1];

    float best = -2.0f;
    int   bg   = IMAXI;
    bool  lq   = false;

    for (int e = o0; e < o1; e++) {
        float v = iou_fn(s_box[e], s_area[e], p, pa);
        int   m = s_m[e];
        // lexicographic (v desc, m asc) == JAX first-index argmax over
        // matched entries; unmatched rows (-1) never win when a match exists.
        if (v > best || (v == best && m < bg)) { best = v; bg = m; }
        lq = lq || (v == s_gm[e]);           // bitwise vs k_rows
    }
    if (best >= 0.6f || lq) atomicAdd(&g_cnt[b * M + bg], 1);
}

// -------- Kernel 4: epilogue + counter reset for next invocation --------
__global__ __launch_bounds__(256) void k_out(float* __restrict__ out,
                                             int BM, int M, int K) {
    int e = blockIdx.x * blockDim.x + threadIdx.x;

    int bm = e / K;
    int j  = e - bm * K;
    int take = 0;
    if (e < BM * K) take = min(g_cnt[bm], K);

    // All readers of g_cnt[bm] are in this block (K divides blockDim for K=4).
    __syncthreads();

    if (e < BM * K) {
        int  m   = bm % M;
        bool val = j < take;
        int  S   = BM * K;
        out[        e] = val ? (float)g_topi[bm * TOPK + j] : -1.0f;
        out[    S + e] = val ? (float)m                     : -1.0f;
        out[2 * S + e] = val ? 1.0f : 0.0f;
        out[3 * S + e] = val ? g_topv[bm * TOPK + j]        : 0.0f;
        if (j == 0) g_cnt[bm] = 0;       // reset for next call
    }
    if (e < NBK) { d_pcnt[e] = 0; d_gcnt[e] = 0; }   // reset buckets
}

// ---------------------------------------------------------------------------
extern "C" void kernel_launch(void* const* d_in, const int* in_sizes, int n_in,
                              void* d_out, int out_size) {
    const float4* props   = (const float4*)d_in[2];
    const int*    pinds   = (const int*)   d_in[3];
    const int*    glabels = (const int*)   d_in[4];
    const float4* gts     = (const float4*)d_in[5];

    const int B  = BB;
    int BN = in_sizes[3];
    int BM = in_sizes[4];
    int N  = BN / B;
    int M  = BM / B;
    int K  = out_size / (4 * BM);
    if (K > TOPK) K = TOPK;
    if (K < 1)    K = 1;

    k_build<<<(BN + BM + 255) / 256, 256>>>(props, gts, pinds, glabels, BN, BM, N, M);
    k_rows <<<(BM * 8 + 255) / 256, 256>>>(glabels, M, BM);
    k_cols <<<dim3((N + 255) / 256, B), 256>>>(pinds, N, M);
    int outThreads = BM * K;
    if (outThreads < NBK) outThreads = NBK;
    k_out  <<<(outThreads + 255) / 256, 256>>>((float*)d_out, BM, M, K);
}